// round 3
// baseline (speedup 1.0000x reference)
#include <cuda_runtime.h>
#include <stdint.h>

#define NCOL   4096
#define TPB    256
#define EPT    16          // elements per thread
#define KSEL   64
#define TGUESS 1.5f        // prefilter guess; exact fallback if it fails
#define CAP    2048        // candidate capacity (expected ~274)

// float -> order-preserving uint32 (larger float => larger unsigned key)
__device__ __forceinline__ uint32_t f2k(float f) {
    uint32_t u = __float_as_uint(f);
    return u ^ (uint32_t)((((int32_t)u) >> 31) | (int32_t)0x80000000);
}
__device__ __forceinline__ float k2f(uint32_t k) {
    uint32_t u = (k & 0x80000000u) ? (k ^ 0x80000000u) : ~k;
    return __uint_as_float(u);
}

// inclusive block scan over TPB=256 uint32 values. wsum: shared[8].
__device__ __forceinline__ uint32_t block_scan_inc(uint32_t val, uint32_t* wsum, int t) {
    __syncthreads();                 // protect wsum WAR from previous use
    int lane = t & 31, w = t >> 5;
#pragma unroll
    for (int off = 1; off < 32; off <<= 1) {
        uint32_t n = __shfl_up_sync(0xffffffffu, val, off);
        if (lane >= off) val += n;
    }
    if (lane == 31) wsum[w] = val;
    __syncthreads();
    if (w == 0) {
        uint32_t s = (lane < 8) ? wsum[lane] : 0u;
#pragma unroll
        for (int off = 1; off < 8; off <<= 1) {
            uint32_t n = __shfl_up_sync(0xffffffffu, s, off);
            if (lane >= off) s += n;
        }
        if (lane < 8) wsum[lane] = s;
    }
    __syncthreads();
    uint32_t base = (w > 0) ? wsum[w - 1] : 0u;
    return val + base;
}

__global__ __launch_bounds__(TPB) void topk_mask_kernel(const float* __restrict__ x,
                                                        float* __restrict__ out) {
    __shared__ uint32_t cand[CAP];            // candidate keys; later aliased as u16 tiebuf[4096]
    __shared__ uint32_t hist[256];
    __shared__ uint32_t wsum[8];
    __shared__ uint32_t s_cnt, s_pos;
    __shared__ uint32_t s_bin, s_above, s_h;
    __shared__ uint32_t keep_bm[NCOL / 32];

    const int t = threadIdx.x;
    const size_t row_off = (size_t)blockIdx.x * NCOL;
    const float4* __restrict__ xr = (const float4*)(x + row_off);
    float4* __restrict__ outr     = (float4*)(out + row_off);

    // ---- coalesced load; raw floats live in registers ----
    float f[EPT];
#pragma unroll
    for (int v = 0; v < EPT / 4; v++) {
        float4 q = xr[v * TPB + t];
        f[4 * v + 0] = q.x; f[4 * v + 1] = q.y;
        f[4 * v + 2] = q.z; f[4 * v + 3] = q.w;
    }

    if (t == 0) { s_cnt = 0; s_pos = 0; }
    __syncthreads();

    // ---- prefilter count: elements strictly above the guess ----
    uint32_t c = 0;
#pragma unroll
    for (int e = 0; e < EPT; e++) c += (f[e] > TGUESS) ? 1u : 0u;
    uint32_t wc = __reduce_add_sync(0xffffffffu, c);
    if ((t & 31) == 0) atomicAdd(&s_cnt, wc);
    __syncthreads();
    const uint32_t C = s_cnt;
    const bool fast = (C >= KSEL && C <= CAP);

    // ---- exact radix select (4x8-bit MSB-first) for the K-th largest key ----
    uint32_t prefix = 0, mmask = 0, kth = KSEL, total_eq = 0;

    if (fast) {
        // gather candidate keys into SMEM (expected ~274 of 4096)
#pragma unroll
        for (int e = 0; e < EPT; e++) {
            if (f[e] > TGUESS) {
                uint32_t p = atomicAdd(&s_pos, 1u);
                cand[p] = f2k(f[e]);
            }
        }
        __syncthreads();
#pragma unroll
        for (int pass = 0; pass < 4; pass++) {
            const int shift = 24 - 8 * pass;
            hist[t] = 0;
            __syncthreads();
            for (uint32_t i = t; i < C; i += TPB) {
                uint32_t kk = cand[i];
                if ((kk & mmask) == prefix)
                    atomicAdd(&hist[(kk >> shift) & 0xFFu], 1u);
            }
            __syncthreads();
            uint32_t h = hist[255 - t];
            uint32_t S = block_scan_inc(h, wsum, t);
            if (S >= kth && (S - h) < kth) {        // unique boundary thread
                s_bin = (uint32_t)(255 - t); s_above = S - h; s_h = h;
            }
            __syncthreads();
            prefix |= (s_bin << shift);
            mmask  |= (0xFFu << shift);
            kth    -= s_above;
            total_eq = s_h;                          // meaningful after last pass
            __syncthreads();
        }
    } else {
        // fallback: exact radix over all elements (keys computed on the fly)
#pragma unroll
        for (int pass = 0; pass < 4; pass++) {
            const int shift = 24 - 8 * pass;
            hist[t] = 0;
            __syncthreads();
#pragma unroll
            for (int e = 0; e < EPT; e++) {
                uint32_t kk = f2k(f[e]);
                if ((kk & mmask) == prefix) {
                    uint32_t bin = (kk >> shift) & 0xFFu;
                    unsigned act = __activemask();
                    unsigned grp = __match_any_sync(act, bin);
                    if ((grp & ((1u << (t & 31)) - 1u)) == 0u)
                        atomicAdd(&hist[bin], (uint32_t)__popc(grp));
                }
            }
            __syncthreads();
            uint32_t h = hist[255 - t];
            uint32_t S = block_scan_inc(h, wsum, t);
            if (S >= kth && (S - h) < kth) {
                s_bin = (uint32_t)(255 - t); s_above = S - h; s_h = h;
            }
            __syncthreads();
            prefix |= (s_bin << shift);
            mmask  |= (0xFFu << shift);
            kth    -= s_above;
            total_eq = s_h;
            __syncthreads();
        }
    }

    const uint32_t need = kth;          // how many == T to keep (lowest columns first)
    const float Tf = k2f(prefix);       // exact K-th largest value
    const bool tie_rank = (total_eq > need);   // rare: must rank ties by column

    if (tie_rank) {
        uint16_t* tiebuf = (uint16_t*)cand;     // reuse: 4096 u16 == CAP u32 bytes
        if (t == 0) s_pos = 0;
        for (int i = t; i < NCOL / 32; i += TPB) keep_bm[i] = 0;
        __syncthreads();
#pragma unroll
        for (int e = 0; e < EPT; e++) {
            if (f[e] == Tf) {
                int v = e >> 2, j = e & 3;
                uint32_t col = (uint32_t)(v * TPB + t) * 4u + (uint32_t)j;
                uint32_t p = atomicAdd(&s_pos, 1u);
                tiebuf[p] = (uint16_t)col;
            }
        }
        __syncthreads();
        uint32_t total = s_pos;
        for (uint32_t i = t; i < total; i += TPB) {
            uint32_t ci = tiebuf[i], r = 0;
            for (uint32_t j = 0; j < total; j++) r += (tiebuf[j] < ci) ? 1u : 0u;
            if (r < need) atomicOr(&keep_bm[ci >> 5], 1u << (ci & 31));
        }
        __syncthreads();
    }

    // ---- masked output straight from registers, coalesced ----
#pragma unroll
    for (int v = 0; v < EPT / 4; v++) {
        float4 o;
        float* op = (float*)&o;
#pragma unroll
        for (int j = 0; j < 4; j++) {
            float fv = f[4 * v + j];
            float val = 0.0f;
            if (fv > Tf) {
                val = fv;
            } else if (fv == Tf) {
                if (!tie_rank) {
                    val = fv;
                } else {
                    uint32_t col = (uint32_t)(v * TPB + t) * 4u + (uint32_t)j;
                    if ((keep_bm[col >> 5] >> (col & 31)) & 1u) val = fv;
                }
            }
            op[j] = val;
        }
        outr[v * TPB + t] = o;
    }
}

extern "C" void kernel_launch(void* const* d_in, const int* in_sizes, int n_in,
                              void* d_out, int out_size) {
    const float* x = (const float*)d_in[0];
    float* out = (float*)d_out;
    int rows = in_sizes[0] / NCOL;
    topk_mask_kernel<<<rows, TPB>>>(x, out);
}

// round 4
// speedup vs baseline: 1.3584x; 1.3584x over previous
#include <cuda_runtime.h>
#include <stdint.h>

#define NCOL   4096
#define TPB    256
#define KSEL   64
#define TGUESS 1.5f        // prefilter guess; exact fallback if it fails
#define CAP    2048        // candidate capacity (expected ~274 per row)

// float -> order-preserving uint32 (larger float => larger unsigned key)
__device__ __forceinline__ uint32_t f2k(float f) {
    uint32_t u = __float_as_uint(f);
    return u ^ (uint32_t)((((int32_t)u) >> 31) | (int32_t)0x80000000);
}
__device__ __forceinline__ float k2f(uint32_t k) {
    uint32_t u = (k & 0x80000000u) ? (k ^ 0x80000000u) : ~k;
    return __uint_as_float(u);
}

// inclusive block scan over TPB=256 uint32 values. wsum: shared[8].
__device__ __forceinline__ uint32_t block_scan_inc(uint32_t val, uint32_t* wsum, int t) {
    __syncthreads();                 // protect wsum WAR from previous use
    int lane = t & 31, w = t >> 5;
#pragma unroll
    for (int off = 1; off < 32; off <<= 1) {
        uint32_t n = __shfl_up_sync(0xffffffffu, val, off);
        if (lane >= off) val += n;
    }
    if (lane == 31) wsum[w] = val;
    __syncthreads();
    if (w == 0) {
        uint32_t s = (lane < 8) ? wsum[lane] : 0u;
#pragma unroll
        for (int off = 1; off < 8; off <<= 1) {
            uint32_t n = __shfl_up_sync(0xffffffffu, s, off);
            if (lane >= off) s += n;
        }
        if (lane < 8) wsum[lane] = s;
    }
    __syncthreads();
    uint32_t base = (w > 0) ? wsum[w - 1] : 0u;
    return val + base;
}

__global__ __launch_bounds__(TPB, 8) void topk_mask_kernel(const float* __restrict__ x,
                                                           float* __restrict__ out) {
    __shared__ uint32_t cand[CAP];            // candidate keys; aliased as u16 tiebuf on tie path
    __shared__ uint32_t hist[256];
    __shared__ uint32_t wsum[8];
    __shared__ uint32_t s_pos, s_bin, s_above, s_h;
    __shared__ uint32_t keep_bm[NCOL / 32];

    const int t    = threadIdx.x;
    const int lane = t & 31;
    const size_t row_off = (size_t)blockIdx.x * NCOL;
    const float4* __restrict__ xr = (const float4*)(x + row_off);
    float4* __restrict__ outr     = (float4*)(out + row_off);

    if (t == 0) s_pos = 0;
    __syncthreads();

    // ---- phase 1: fused load + prefilter + candidate gather (low register liveness) ----
#pragma unroll
    for (int h = 0; h < 2; h++) {
        float4 a = xr[(2 * h + 0) * TPB + t];
        float4 b = xr[(2 * h + 1) * TPB + t];
        const float* p8 = (const float*)&a;     // a then b are contiguous? not guaranteed;
        float vals[8] = {a.x, a.y, a.z, a.w, b.x, b.y, b.z, b.w};
#pragma unroll
        for (int j = 0; j < 8; j++) {
            float fv = vals[j];
            if (fv > TGUESS) {
                uint32_t p = atomicAdd(&s_pos, 1u);
                if (p < CAP) cand[p] = f2k(fv);
            }
        }
        (void)p8;
    }
    __syncthreads();
    const uint32_t C = s_pos;
    const bool fast = (C >= KSEL && C <= CAP);

    // ---- phase 2: exact radix select (4x8-bit MSB-first) for the K-th largest key ----
    uint32_t prefix = 0, mmask = 0, kth = KSEL, total_eq = 0;

    if (fast) {
#pragma unroll
        for (int pass = 0; pass < 4; pass++) {
            const int shift = 24 - 8 * pass;
            hist[t] = 0;
            __syncthreads();
            for (uint32_t i = t; i < C; i += TPB) {
                uint32_t kk = cand[i];
                if ((kk & mmask) == prefix) {
                    uint32_t bin = (kk >> shift) & 0xFFu;
                    unsigned act = __activemask();
                    unsigned grp = __match_any_sync(act, bin);
                    if ((grp & ((1u << lane) - 1u)) == 0u)
                        atomicAdd(&hist[bin], (uint32_t)__popc(grp));
                }
            }
            __syncthreads();
            uint32_t hh = hist[255 - t];
            uint32_t S = block_scan_inc(hh, wsum, t);
            if (S >= kth && (S - hh) < kth) {       // unique boundary thread
                s_bin = (uint32_t)(255 - t); s_above = S - hh; s_h = hh;
            }
            __syncthreads();
            prefix |= (s_bin << shift);
            mmask  |= (0xFFu << shift);
            kth    -= s_above;
            total_eq = s_h;                          // meaningful after last pass
            __syncthreads();
        }
    } else {
        // fallback: exact radix over the whole row, re-reading from L2 (rare path)
#pragma unroll 1
        for (int pass = 0; pass < 4; pass++) {
            const int shift = 24 - 8 * pass;
            hist[t] = 0;
            __syncthreads();
            for (int i = t; i < NCOL; i += TPB) {
                uint32_t kk = f2k(x[row_off + i]);
                if ((kk & mmask) == prefix) {
                    uint32_t bin = (kk >> shift) & 0xFFu;
                    unsigned act = __activemask();
                    unsigned grp = __match_any_sync(act, bin);
                    if ((grp & ((1u << lane) - 1u)) == 0u)
                        atomicAdd(&hist[bin], (uint32_t)__popc(grp));
                }
            }
            __syncthreads();
            uint32_t hh = hist[255 - t];
            uint32_t S = block_scan_inc(hh, wsum, t);
            if (S >= kth && (S - hh) < kth) {
                s_bin = (uint32_t)(255 - t); s_above = S - hh; s_h = hh;
            }
            __syncthreads();
            prefix |= (s_bin << shift);
            mmask  |= (0xFFu << shift);
            kth    -= s_above;
            total_eq = s_h;
            __syncthreads();
        }
    }

    const uint32_t need = kth;                 // how many == T to keep (lowest cols first)
    const float Tf = k2f(prefix);              // exact K-th largest value
    const bool tie_rank = (total_eq > need);   // rare: rank ties by column

    if (tie_rank) {
        uint16_t* tiebuf = (uint16_t*)cand;    // 4096 u16 fits in CAP u32 bytes
        if (t == 0) s_pos = 0;
        for (int i = t; i < NCOL / 32; i += TPB) keep_bm[i] = 0;
        __syncthreads();
        for (int i = t; i < NCOL; i += TPB) {
            if (x[row_off + i] == Tf) {
                uint32_t p = atomicAdd(&s_pos, 1u);
                tiebuf[p] = (uint16_t)i;
            }
        }
        __syncthreads();
        uint32_t total = s_pos;
        for (uint32_t i = t; i < total; i += TPB) {
            uint32_t ci = tiebuf[i], r = 0;
            for (uint32_t j = 0; j < total; j++) r += (tiebuf[j] < ci) ? 1u : 0u;
            if (r < need) atomicOr(&keep_bm[ci >> 5], 1u << (ci & 31));
        }
        __syncthreads();
    }

    // ---- phase 3: masked output; re-read row (L2-resident), coalesced write ----
#pragma unroll
    for (int v = 0; v < 4; v++) {
        float4 q = xr[v * TPB + t];
        float4 o;
        float* ip = (float*)&q;
        float* op = (float*)&o;
#pragma unroll
        for (int j = 0; j < 4; j++) {
            float fv = ip[j];
            float val = 0.0f;
            if (fv > Tf) {
                val = fv;
            } else if (fv == Tf) {
                if (!tie_rank) {
                    val = fv;
                } else {
                    uint32_t col = (uint32_t)(v * TPB + t) * 4u + (uint32_t)j;
                    if ((keep_bm[col >> 5] >> (col & 31)) & 1u) val = fv;
                }
            }
            op[j] = val;
        }
        outr[v * TPB + t] = o;
    }
}

extern "C" void kernel_launch(void* const* d_in, const int* in_sizes, int n_in,
                              void* d_out, int out_size) {
    const float* x = (const float*)d_in[0];
    float* out = (float*)d_out;
    int rows = in_sizes[0] / NCOL;
    topk_mask_kernel<<<rows, TPB>>>(x, out);
}